// round 14
// baseline (speedup 1.0000x reference)
#include <cuda_runtime.h>
#include <cuda_fp16.h>
#include <cstdint>

// out[M,11008] = x[M,4096] @ dequant(qweight) + bias
// fp16 mma.sync.m16n8k16 + ldmatrix + cp.async 3-stage A / 2-stage B.
// R3 skeleton + PRMT-free dequant (column perm fixed in epilogue) +
// instruction-interleaved produce(t+1) inside compute(t).

#define KDIM    4096
#define NDIM    11008
#define NPACK   1376
#define BM      128
#define BN      128
#define BK      64
#define NCHUNK  64
#define MAXM    2048
#define A_STAGE 16384
#define B_STAGE 16384
#define SMEM_DYN (3*A_STAGE + 2*B_STAGE + 1024)

__device__ __half x16g[(size_t)MAXM * KDIM];

__device__ __forceinline__ uint32_t smem_u32(const void* p) {
    uint32_t a;
    asm("{ .reg .u64 t; cvta.to.shared.u64 t, %1; cvt.u32.u64 %0, t; }" : "=r"(a) : "l"(p));
    return a;
}
__device__ __forceinline__ uint32_t sw128(uint32_t o) { return o ^ ((o >> 3) & 0x70); }

#define LDSM_X4(r0,r1,r2,r3,addr) \
    asm volatile("ldmatrix.sync.aligned.m8n8.x4.shared.b16 {%0,%1,%2,%3}, [%4];" \
        : "=r"(r0),"=r"(r1),"=r"(r2),"=r"(r3) : "r"(addr))
#define LDSM_X4_T(r0,r1,r2,r3,addr) \
    asm volatile("ldmatrix.sync.aligned.m8n8.x4.trans.shared.b16 {%0,%1,%2,%3}, [%4];" \
        : "=r"(r0),"=r"(r1),"=r"(r2),"=r"(r3) : "r"(addr))

__device__ __forceinline__ void mma16816(float* d, const uint32_t* a,
                                         uint32_t b0, uint32_t b1) {
    asm volatile(
        "mma.sync.aligned.m16n8k16.row.col.f32.f16.f16.f32 "
        "{%0,%1,%2,%3}, {%4,%5,%6,%7}, {%8,%9}, {%0,%1,%2,%3};"
        : "+f"(d[0]), "+f"(d[1]), "+f"(d[2]), "+f"(d[3])
        : "r"(a[0]), "r"(a[1]), "r"(a[2]), "r"(a[3]), "r"(b0), "r"(b1));
}
__device__ __forceinline__ void cp16(uint32_t saddr, const void* g) {
    asm volatile("cp.async.cg.shared.global [%0], [%1], 16;" :: "r"(saddr), "l"(g));
}

// ---------------- prepass: x fp32 -> fp16 ----------------
__global__ __launch_bounds__(256) void cvt_x(const float* __restrict__ x, int M) {
    const size_t e = ((size_t)blockIdx.x * 256 + threadIdx.x) * 8;
    if (e >= (size_t)MAXM * KDIM) return;
    const int row = (int)(e >> 12);
    uint4 v;
    if (row < M) {
        const float4 f0 = reinterpret_cast<const float4*>(x + e)[0];
        const float4 f1 = reinterpret_cast<const float4*>(x + e)[1];
        __half2 p0 = __floats2half2_rn(f0.x, f0.y);
        __half2 p1 = __floats2half2_rn(f0.z, f0.w);
        __half2 p2 = __floats2half2_rn(f1.x, f1.y);
        __half2 p3 = __floats2half2_rn(f1.z, f1.w);
        v.x = *reinterpret_cast<uint32_t*>(&p0);
        v.y = *reinterpret_cast<uint32_t*>(&p1);
        v.z = *reinterpret_cast<uint32_t*>(&p2);
        v.w = *reinterpret_cast<uint32_t*>(&p3);
    } else v = make_uint4(0, 0, 0, 0);
    *reinterpret_cast<uint4*>(x16g + e) = v;
}

// ---------------- main GEMM ----------------
__global__ __launch_bounds__(256, 2) void qlin_f16(
    const int*   __restrict__ qw,
    const int*   __restrict__ qz,
    const float* __restrict__ sc,
    const float* __restrict__ bias,
    float*       __restrict__ out,
    int M)
{
    extern __shared__ char smem_raw[];
    const uint32_t sb0 = smem_u32(smem_raw);
    const uint32_t sb  = (sb0 + 1023) & ~1023u;
    const uint32_t sA[3] = { sb, sb + A_STAGE, sb + 2 * A_STAGE };
    const uint32_t sB[2] = { sb + 3 * A_STAGE, sb + 3 * A_STAGE + B_STAGE };

    const int tid  = threadIdx.x;
    const int lane = tid & 31;
    const int wid  = tid >> 5;
    const int wm   = wid >> 1;          // 0..3
    const int wn   = wid & 1;           // 0..1
    const int m0   = blockIdx.y * BM;
    const int n0   = blockIdx.x * BN;

    float acc[2][8][4];
    #pragma unroll
    for (int im = 0; im < 2; im++)
        #pragma unroll
        for (int jn = 0; jn < 8; jn++)
            #pragma unroll
            for (int r = 0; r < 4; r++) acc[im][jn][r] = 0.f;

    // ---- A cp.async: 1024 16B lines, 4 per thread ----
    auto cpA = [&](int t, int stg) {
        const __half* src = x16g + (size_t)m0 * KDIM + t * BK;
        #pragma unroll
        for (int p = 0; p < 4; p++) {
            const int c   = tid + p * 256;
            const int row = c >> 3, kc = c & 7;
            cp16(sA[stg] + sw128((uint32_t)(row * 128 + kc * 16)),
                 src + (size_t)row * KDIM + kc * 8);
        }
        asm volatile("cp.async.commit_group;");
    };

    // ---- B dequant coords ----
    const int nb = tid & 15;            // packed col (8 n each)
    const int kq = tid >> 4;            // 0..15
    const size_t nbG = (size_t)(n0 >> 3) + nb;
    __half2 zc[4], s2[4];
    int qbuf[2][4];

    auto refresh_group = [&](int g) {
        const uint32_t zq = (uint32_t)qz[(size_t)g * NPACK + nbG];
        #pragma unroll
        for (int j = 0; j < 4; j++) {
            uint32_t p = ((zq >> (4 * j)) & 0x000F000Fu) | 0x64006400u;
            zc[j] = *reinterpret_cast<__half2*>(&p);
        }
        const float4* sp = reinterpret_cast<const float4*>(
            sc + (size_t)g * NDIM + n0 + nb * 8);
        const float4 sa = sp[0], sbv = sp[1];
        s2[0] = __floats2half2_rn(sa.x, sbv.x);
        s2[1] = __floats2half2_rn(sa.y, sbv.y);
        s2[2] = __floats2half2_rn(sa.z, sbv.z);
        s2[3] = __floats2half2_rn(sa.w, sbv.w);
    };
    auto ldgQ = [&](int t, int* q) {
        #pragma unroll
        for (int i = 0; i < 4; i++)
            q[i] = qw[(size_t)(t * BK + kq + 16 * i) * NPACK + nbG];
    };
    // one dequant packet: word i -> 16 halves, stored in natural pair order
    // memory column order within octet: [n0,n4,n1,n5,n2,n6,n3,n7]
    auto dqPacket = [&](int stg, int i, const int* q) {
        char* Bsub = smem_raw + (sB[stg] - sb0) + (nb >> 3) * 8192;
        const uint32_t cb = (uint32_t)((nb & 7) * 16);
        const int k = kq + 16 * i;
        const uint32_t qv = (uint32_t)q[i];
        uint4 v;
        uint32_t w;
        {
            uint32_t p = (qv & 0x000F000Fu) | 0x64006400u;
            __half2 hv = __hmul2(__hsub2(*reinterpret_cast<__half2*>(&p), zc[0]), s2[0]);
            v.x = *reinterpret_cast<uint32_t*>(&hv);
        }
        {
            uint32_t p = ((qv >> 4) & 0x000F000Fu) | 0x64006400u;
            __half2 hv = __hmul2(__hsub2(*reinterpret_cast<__half2*>(&p), zc[1]), s2[1]);
            v.y = *reinterpret_cast<uint32_t*>(&hv);
        }
        {
            uint32_t p = ((qv >> 8) & 0x000F000Fu) | 0x64006400u;
            __half2 hv = __hmul2(__hsub2(*reinterpret_cast<__half2*>(&p), zc[2]), s2[2]);
            v.z = *reinterpret_cast<uint32_t*>(&hv);
        }
        {
            uint32_t p = ((qv >> 12) & 0x000F000Fu) | 0x64006400u;
            __half2 hv = __hmul2(__hsub2(*reinterpret_cast<__half2*>(&p), zc[3]), s2[3]);
            v.w = *reinterpret_cast<uint32_t*>(&hv);
        }
        (void)w;
        *reinterpret_cast<uint4*>(Bsub + sw128((uint32_t)(k * 128) + cb)) = v;
    };

    const int lr = lane & 15, lc = lane >> 4;

    // ---- prologue ----
    ldgQ(0, qbuf[0]);
    refresh_group(0);
    cpA(0, 0);
    cpA(1, 1);
    #pragma unroll
    for (int i = 0; i < 4; i++) dqPacket(0, i, qbuf[0]);   // B chunk 0 -> stage 0
    ldgQ(1, qbuf[1]);
    asm volatile("cp.async.wait_group 1;");                // A0 ready
    __syncthreads();

    // ---- main loop: compute(t) with produce(t+1) interleaved ----
    for (int t = 0; t < NCHUNK; t++) {
        const int aStg = t % 3;
        const int bStg = t & 1;
        const bool prod = (t + 1 < NCHUNK);
        const int* qc = qbuf[(t + 1) & 1];

        if (prod && (t & 1)) refresh_group((t + 1) >> 1);
        if (t + 2 < NCHUNK) { ldgQ(t + 2, qbuf[t & 1]); cpA(t + 2, (t + 2) % 3); }

        const uint32_t aB = sA[aStg];
        const uint32_t bB = sB[bStg] + wn * 8192;
        #pragma unroll
        for (int ks = 0; ks < 4; ks++) {
            uint32_t a[2][4];
            #pragma unroll
            for (int im = 0; im < 2; im++) {
                const uint32_t addr = aB + sw128(
                    (uint32_t)((wm * 32 + im * 16 + lr) * 128 + ks * 32 + lc * 16));
                LDSM_X4(a[im][0], a[im][1], a[im][2], a[im][3], addr);
            }
            uint32_t b[4][4];
            #pragma unroll
            for (int jn = 0; jn < 4; jn++) {
                const uint32_t addr = bB + sw128(
                    (uint32_t)((ks * 16 + lr) * 128 + jn * 32 + lc * 16));
                LDSM_X4_T(b[jn][0], b[jn][1], b[jn][2], b[jn][3], addr);
            }
            if (prod) dqPacket((t + 1) & 1, ks, qc);   // ALU fills MMA shadow
            #pragma unroll
            for (int jn = 0; jn < 4; jn++) {
                #pragma unroll
                for (int im = 0; im < 2; im++) {
                    mma16816(acc[im][2 * jn],     a[im], b[jn][0], b[jn][1]);
                    mma16816(acc[im][2 * jn + 1], a[im], b[jn][2], b[jn][3]);
                }
            }
        }

        if (prod) {
            asm volatile("cp.async.wait_group 1;");    // A(t+1) ready
            __syncthreads();
        }
    }

    // ---- epilogue: undo column perm [0,4,1,5,2,6,3,7] ----
    const int q4 = lane & 3;
    #pragma unroll
    for (int im = 0; im < 2; im++) {
        const int row = m0 + wm * 32 + im * 16 + (lane >> 2);
        #pragma unroll
        for (int jn = 0; jn < 8; jn++) {
            const int base = n0 + wn * 64 + jn * 8;
            const int col0 = base + q4;        // fragment c=2q
            const int col1 = base + q4 + 4;    // fragment c=2q+1
            const float b0 = bias[col0], b1 = bias[col1];
            const float* c = acc[im][jn];
            if (row < M) {
                out[(size_t)row * NDIM + col0] = c[0] + b0;
                out[(size_t)row * NDIM + col1] = c[1] + b1;
            }
            if (row + 8 < M) {
                out[(size_t)(row + 8) * NDIM + col0] = c[2] + b0;
                out[(size_t)(row + 8) * NDIM + col1] = c[3] + b1;
            }
        }
    }
}

extern "C" void kernel_launch(void* const* d_in, const int* in_sizes, int n_in,
                              void* d_out, int out_size)
{
    const float* x    = (const float*)d_in[0];
    const int*   qw   = (const int*)  d_in[1];
    const int*   qz   = (const int*)  d_in[2];
    const float* sc   = (const float*)d_in[3];
    const float* bias = (const float*)d_in[4];
    float*       out  = (float*)d_out;

    int M = in_sizes[0] / KDIM;
    if (M > MAXM) M = MAXM;

    cvt_x<<<(MAXM * KDIM / 8 + 255) / 256, 256>>>(x, M);

    cudaFuncSetAttribute(qlin_f16, cudaFuncAttributeMaxDynamicSharedMemorySize, SMEM_DYN);
    dim3 grid(NDIM / BN, (M + BM - 1) / BM);
    qlin_f16<<<grid, 256, SMEM_DYN>>>(qw, qz, sc, bias, out, M);
}

// round 15
// speedup vs baseline: 1.1292x; 1.1292x over previous
#include <cuda_runtime.h>
#include <cuda_fp16.h>
#include <cstdint>

// out[M,11008] = x[M,4096] @ dequant(qweight) + bias
// fp16 mma.sync.m16n8k16 + ldmatrix + cp.async 3-stage A / 2-stage B.
// R3 champion with ONE change: dequant(t+1) issued BEFORE compute(t)
// so STS drains during compute and the barrier is adjacent to MMA work.

#define KDIM    4096
#define NDIM    11008
#define NPACK   1376
#define BM      128
#define BN      128
#define BK      64
#define NCHUNK  64
#define MAXM    2048
#define A_STAGE 16384
#define B_STAGE 16384
#define SMEM_DYN (3*A_STAGE + 2*B_STAGE + 1024)

__device__ __half x16g[(size_t)MAXM * KDIM];

__device__ __forceinline__ uint32_t smem_u32(const void* p) {
    uint32_t a;
    asm("{ .reg .u64 t; cvta.to.shared.u64 t, %1; cvt.u32.u64 %0, t; }" : "=r"(a) : "l"(p));
    return a;
}
__device__ __forceinline__ uint32_t sw128(uint32_t o) { return o ^ ((o >> 3) & 0x70); }

#define LDSM_X4(r0,r1,r2,r3,addr) \
    asm volatile("ldmatrix.sync.aligned.m8n8.x4.shared.b16 {%0,%1,%2,%3}, [%4];" \
        : "=r"(r0),"=r"(r1),"=r"(r2),"=r"(r3) : "r"(addr))
#define LDSM_X4_T(r0,r1,r2,r3,addr) \
    asm volatile("ldmatrix.sync.aligned.m8n8.x4.trans.shared.b16 {%0,%1,%2,%3}, [%4];" \
        : "=r"(r0),"=r"(r1),"=r"(r2),"=r"(r3) : "r"(addr))

__device__ __forceinline__ void mma16816(float* d, const uint32_t* a,
                                         uint32_t b0, uint32_t b1) {
    asm volatile(
        "mma.sync.aligned.m16n8k16.row.col.f32.f16.f16.f32 "
        "{%0,%1,%2,%3}, {%4,%5,%6,%7}, {%8,%9}, {%0,%1,%2,%3};"
        : "+f"(d[0]), "+f"(d[1]), "+f"(d[2]), "+f"(d[3])
        : "r"(a[0]), "r"(a[1]), "r"(a[2]), "r"(a[3]), "r"(b0), "r"(b1));
}
__device__ __forceinline__ void cp16(uint32_t saddr, const void* g) {
    asm volatile("cp.async.cg.shared.global [%0], [%1], 16;" :: "r"(saddr), "l"(g));
}

// ---------------- prepass: x fp32 -> fp16 (rows >= M zero-filled) ----------------
__global__ __launch_bounds__(256) void cvt_x(const float* __restrict__ x, int M) {
    const size_t e = ((size_t)blockIdx.x * 256 + threadIdx.x) * 8;
    if (e >= (size_t)MAXM * KDIM) return;
    const int row = (int)(e >> 12);
    uint4 v;
    if (row < M) {
        const float4 f0 = reinterpret_cast<const float4*>(x + e)[0];
        const float4 f1 = reinterpret_cast<const float4*>(x + e)[1];
        __half2 p0 = __floats2half2_rn(f0.x, f0.y);
        __half2 p1 = __floats2half2_rn(f0.z, f0.w);
        __half2 p2 = __floats2half2_rn(f1.x, f1.y);
        __half2 p3 = __floats2half2_rn(f1.z, f1.w);
        v.x = *reinterpret_cast<uint32_t*>(&p0);
        v.y = *reinterpret_cast<uint32_t*>(&p1);
        v.z = *reinterpret_cast<uint32_t*>(&p2);
        v.w = *reinterpret_cast<uint32_t*>(&p3);
    } else v = make_uint4(0, 0, 0, 0);
    *reinterpret_cast<uint4*>(x16g + e) = v;
}

// ---------------- main GEMM ----------------
__global__ __launch_bounds__(256, 2) void qlin_f16(
    const int*   __restrict__ qw,
    const int*   __restrict__ qz,
    const float* __restrict__ sc,
    const float* __restrict__ bias,
    float*       __restrict__ out,
    int M)
{
    extern __shared__ char smem_raw[];
    const uint32_t sb0 = smem_u32(smem_raw);
    const uint32_t sb  = (sb0 + 1023) & ~1023u;
    const uint32_t sA[3] = { sb, sb + A_STAGE, sb + 2 * A_STAGE };
    const uint32_t sB[2] = { sb + 3 * A_STAGE, sb + 3 * A_STAGE + B_STAGE };

    const int tid  = threadIdx.x;
    const int lane = tid & 31;
    const int wid  = tid >> 5;
    const int wm   = wid >> 1;          // 0..3
    const int wn   = wid & 1;           // 0..1
    const int m0   = blockIdx.y * BM;
    const int n0   = blockIdx.x * BN;

    float acc[2][8][4];
    #pragma unroll
    for (int im = 0; im < 2; im++)
        #pragma unroll
        for (int jn = 0; jn < 8; jn++)
            #pragma unroll
            for (int r = 0; r < 4; r++) acc[im][jn][r] = 0.f;

    // ---- A cp.async: 1024 16B lines, 4 per thread ----
    auto cpA = [&](int t, int stg) {
        const __half* src = x16g + (size_t)m0 * KDIM + t * BK;
        #pragma unroll
        for (int p = 0; p < 4; p++) {
            const int c   = tid + p * 256;
            const int row = c >> 3, kc = c & 7;
            cp16(sA[stg] + sw128((uint32_t)(row * 128 + kc * 16)),
                 src + (size_t)row * KDIM + kc * 8);
        }
        asm volatile("cp.async.commit_group;");
    };

    // ---- B dequant coords ----
    const int nb = tid & 15;            // packed col (8 n each)
    const int kq = tid >> 4;            // 0..15
    const size_t nbG = (size_t)(n0 >> 3) + nb;
    __half2 zc[4], s2[4];
    int qbuf[2][4];

    auto refresh_group = [&](int g) {
        const uint32_t zq = (uint32_t)qz[(size_t)g * NPACK + nbG];
        #pragma unroll
        for (int j = 0; j < 4; j++) {
            uint32_t p = ((zq >> (4 * j)) & 0x000F000Fu) | 0x64006400u;
            zc[j] = *reinterpret_cast<__half2*>(&p);
        }
        const float4* sp = reinterpret_cast<const float4*>(
            sc + (size_t)g * NDIM + n0 + nb * 8);
        const float4 sa = sp[0], sbv = sp[1];
        s2[0] = __floats2half2_rn(sa.x, sbv.x);
        s2[1] = __floats2half2_rn(sa.y, sbv.y);
        s2[2] = __floats2half2_rn(sa.z, sbv.z);
        s2[3] = __floats2half2_rn(sa.w, sbv.w);
    };
    auto ldgQ = [&](int t, int* q) {
        #pragma unroll
        for (int i = 0; i < 4; i++)
            q[i] = qw[(size_t)(t * BK + kq + 16 * i) * NPACK + nbG];
    };
    auto dequantB = [&](int stg, const int* q) {
        char* Bsub = smem_raw + (sB[stg] - sb0) + (nb >> 3) * 8192;
        const uint32_t cb = (uint32_t)((nb & 7) * 16);
        #pragma unroll
        for (int i = 0; i < 4; i++) {
            const int k = kq + 16 * i;
            const uint32_t qv = (uint32_t)q[i];
            uint32_t w[4];
            #pragma unroll
            for (int j = 0; j < 4; j++) {
                uint32_t p = ((qv >> (4 * j)) & 0x000F000Fu) | 0x64006400u;
                __half2 hv = __hmul2(__hsub2(*reinterpret_cast<__half2*>(&p), zc[j]), s2[j]);
                w[j] = *reinterpret_cast<uint32_t*>(&hv);
            }
            uint4 v;   // pair reorder -> n0..n7 memory order
            v.x = __byte_perm(w[0], w[1], 0x5410);
            v.y = __byte_perm(w[2], w[3], 0x5410);
            v.z = __byte_perm(w[0], w[1], 0x7632);
            v.w = __byte_perm(w[2], w[3], 0x7632);
            *reinterpret_cast<uint4*>(Bsub + sw128((uint32_t)(k * 128) + cb)) = v;
        }
    };

    const int lr = lane & 15, lc = lane >> 4;
    auto compute = [&](int aStg, int bStg) {
        const uint32_t aB = sA[aStg];
        const uint32_t bB = sB[bStg] + wn * 8192;
        #pragma unroll
        for (int ks = 0; ks < 4; ks++) {
            uint32_t a[2][4];
            #pragma unroll
            for (int im = 0; im < 2; im++) {
                const uint32_t addr = aB + sw128(
                    (uint32_t)((wm * 32 + im * 16 + lr) * 128 + ks * 32 + lc * 16));
                LDSM_X4(a[im][0], a[im][1], a[im][2], a[im][3], addr);
            }
            #pragma unroll
            for (int jn = 0; jn < 4; jn++) {
                uint32_t b0, b1, b2, b3;
                const uint32_t addr = bB + sw128(
                    (uint32_t)((ks * 16 + lr) * 128 + jn * 32 + lc * 16));
                LDSM_X4_T(b0, b1, b2, b3, addr);
                #pragma unroll
                for (int im = 0; im < 2; im++) {
                    mma16816(acc[im][2 * jn],     a[im], b0, b1);
                    mma16816(acc[im][2 * jn + 1], a[im], b2, b3);
                }
            }
        }
    };

    // ---- prologue ----
    ldgQ(0, qbuf[0]);
    refresh_group(0);
    cpA(0, 0);
    cpA(1, 1);
    dequantB(0, qbuf[0]);              // B chunk 0 -> stage 0
    ldgQ(1, qbuf[1]);
    asm volatile("cp.async.wait_group 1;");   // A0 ready
    __syncthreads();

    // ---- main loop: dequant(t+1) BEFORE compute(t) ----
    for (int t = 0; t < NCHUNK; t++) {
        if (t + 2 < NCHUNK) cpA(t + 2, (t + 2) % 3);
        if (t + 1 < NCHUNK) {
            if (((t + 1) & 1) == 0) refresh_group((t + 1) >> 1);
            dequantB((t + 1) & 1, qbuf[(t + 1) & 1]);   // STS drains under compute
            if (t + 2 < NCHUNK) ldgQ(t + 2, qbuf[t & 1]);
        }
        compute(t % 3, t & 1);
        if (t + 1 < NCHUNK) {
            asm volatile("cp.async.wait_group 1;");     // A(t+1) ready
            __syncthreads();
        }
    }

    // ---- epilogue ----
    #pragma unroll
    for (int im = 0; im < 2; im++) {
        const int row = m0 + wm * 32 + im * 16 + (lane >> 2);
        #pragma unroll
        for (int jn = 0; jn < 8; jn++) {
            const int col = n0 + wn * 64 + jn * 8 + (lane & 3) * 2;
            const float b0 = bias[col], b1 = bias[col + 1];
            const float* c = acc[im][jn];
            if (row < M)
                *reinterpret_cast<float2*>(out + (size_t)row * NDIM + col) =
                    make_float2(c[0] + b0, c[1] + b1);
            if (row + 8 < M)
                *reinterpret_cast<float2*>(out + (size_t)(row + 8) * NDIM + col) =
                    make_float2(c[2] + b0, c[3] + b1);
        }
    }
}

extern "C" void kernel_launch(void* const* d_in, const int* in_sizes, int n_in,
                              void* d_out, int out_size)
{
    const float* x    = (const float*)d_in[0];
    const int*   qw   = (const int*)  d_in[1];
    const int*   qz   = (const int*)  d_in[2];
    const float* sc   = (const float*)d_in[3];
    const float* bias = (const float*)d_in[4];
    float*       out  = (float*)d_out;

    int M = in_sizes[0] / KDIM;
    if (M > MAXM) M = MAXM;

    cvt_x<<<(MAXM * KDIM / 8 + 255) / 256, 256>>>(x, M);

    cudaFuncSetAttribute(qlin_f16, cudaFuncAttributeMaxDynamicSharedMemorySize, SMEM_DYN);
    dim3 grid(NDIM / BN, (M + BM - 1) / BM);
    qlin_f16<<<grid, 256, SMEM_DYN>>>(qw, qz, sc, bias, out, M);
}